// round 6
// baseline (speedup 1.0000x reference)
#include <cuda_runtime.h>
#include <cstdint>

#define DINLINE __device__ __forceinline__

namespace {
constexpr int kTlen = 1024;
constexpr int kF = 64;
constexpr int kH = 256;
constexpr int kK = 320;          // vec row: 16 slices x [16 h | 4 x] interleaved
constexpr int kNJ = 16;          // CTAs per barrier group (hidden stripes)
constexpr int kBT = 16;          // batch rows per CTA
constexpr int kNS = 16;          // k-slices (split-K)
constexpr int kKPh = 8;          // h f32x2 pairs per slice
constexpr int kKPx = 2;          // x f32x2 pairs per slice
constexpr int kThreads = 256;
constexpr int kCtas = 128;       // 8 batch stripes x 16 hidden stripes
constexpr int kSmemBytes = 120 * 1024;  // force 1 CTA/SM => all CTAs resident
}

__device__ float g_h[2][128 * 256];
__device__ unsigned g_cnt[8 * 64];  // one counter per group, 256B apart

__global__ void init_barriers_kernel() {
  if (threadIdx.x < 8) g_cnt[threadIdx.x * 64] = 0u;
}

DINLINE unsigned long long pack2(float lo, float hi) {
  unsigned long long r;
  asm("mov.b64 %0, {%1, %2};" : "=l"(r) : "f"(lo), "f"(hi));
  return r;
}
DINLINE void ffma2(unsigned long long& d, unsigned long long a, unsigned long long b) {
  asm("fma.rn.f32x2 %0, %1, %2, %0;" : "+l"(d) : "l"(a), "l"(b));
}
DINLINE float2 unpack2(unsigned long long v) {
  float lo, hi;
  asm("mov.b64 {%0, %1}, %2;" : "=f"(lo), "=f"(hi) : "l"(v));
  return make_float2(lo, hi);
}
DINLINE float sigmoidf_(float x) { return __fdividef(1.0f, 1.0f + __expf(-x)); }
DINLINE float tanhf_(float x) {
  const float e = __expf(2.0f * x);
  return 1.0f - __fdividef(2.0f, e + 1.0f);
}

__global__ void __launch_bounds__(kThreads, 1)
lstm_seq2seq_kernel(const float* __restrict__ ts,
                    const float* __restrict__ Wih_e, const float* __restrict__ Whh_e,
                    const float* __restrict__ b_e,
                    const float* __restrict__ Wih_d, const float* __restrict__ Whh_d,
                    const float* __restrict__ b_d,
                    const float* __restrict__ Wout, const float* __restrict__ bout,
                    float* __restrict__ out) {
  extern __shared__ float smem[];
  float* vec = smem;                         // [16 b][320] interleaved [16h|4x]*16
  float* partial = smem + kBT * kK;          // [16 slices][16 b][64 c] gate-major
  float* wout_s = partial + kNS * kBT * 64;  // [4][256]
  float* bout_s = wout_s + 4 * kH;           // [4]

  const int tid = threadIdx.x;
  const int jstripe = blockIdx.x & (kNJ - 1);
  const int bstripe = blockIdx.x >> 4;

  const int slice = tid >> 4;   // 0..15  (GEMM k-slice)
  const int cg = tid & 15;      // 0..15  (gate-col group of 4)
  const int bl = tid >> 4;      // update: local batch row
  const int jj = tid & 15;      // update: local hidden col
  const int xrow = tid >> 4, xs = tid & 15;  // staging: (row, slice)

  unsigned* cnt = &g_cnt[bstripe * 64];
  unsigned barno = 0;           // tracked by ALL threads (identical)

  // h0 = 0 for owned (b,j); stage W_out tile + b_out
  g_h[0][(bstripe * kBT + bl) * kH + jstripe * 16 + jj] = 0.0f;
  for (int idx = tid; idx < 4 * kH; idx += kThreads)
    wout_s[idx] = Wout[jstripe * 4 * kH + idx];
  if (tid < 4) bout_s[tid] = bout[jstripe * 4 + tid];

  unsigned long long w2[4][kKPh];   // h weights (f32x2 k-pairs, registers)
  unsigned long long wx2[4][kKPx];  // x weights
  float bias[4];
  float cst = 0.0f;                 // cell state in register across all steps

  auto load_w = [&](const float* Wih, const float* Whh, const float* bv) {
#pragma unroll
    for (int cc = 0; cc < 4; ++cc) {
      const int c = cg * 4 + cc;  // gate col 0..63 = gate*16 + j
      const int row = (c >> 4) * kH + jstripe * 16 + (c & 15);
#pragma unroll
      for (int kp = 0; kp < kKPh; ++kp) {
        const int k = slice * 16 + 2 * kp;
        w2[cc][kp] = pack2(Whh[row * kH + k], Whh[row * kH + k + 1]);
      }
#pragma unroll
      for (int kp = 0; kp < kKPx; ++kp) {
        const int k = slice * 4 + 2 * kp;
        wx2[cc][kp] = pack2(Wih[row * kF + k], Wih[row * kF + k + 1]);
      }
    }
    const int jg = jstripe * 16 + jj;
#pragma unroll
    for (int g = 0; g < 4; ++g) bias[g] = bv[g * kH + jg];
  };

  // monotonic single-atomic barrier; arrive bumps barno in every thread
  auto arrive = [&]() {
    __syncthreads();  // all h stores of this CTA issued
    ++barno;
    if (tid == 0) {
      __threadfence();
      atomicAdd(cnt, 1u);  // result unused -> RED
    }
  };
  // all-thread spin (coalesced to one L2 request per warp); acquire per thread
  auto spin = [&]() {
    const unsigned target = (unsigned)kNJ * barno;
    unsigned v;
    do {
      asm volatile("ld.acquire.gpu.u32 %0, [%1];" : "=r"(v) : "l"(cnt));
    } while ((int)(v - target) < 0);
  };

  const unsigned long long* vec2 = reinterpret_cast<const unsigned long long*>(vec);

  auto step = [&](int t, int buf, bool dec) {
    // ============ pre-wait: h-independent work ============
    // stage x(t) into interleaved x-slots: vec[row][s*20+16..19] = x[row][4s..]
    {
      float4 vx = reinterpret_cast<const float4*>(
          ts + (((bstripe * kBT + xrow) * kTlen + t) * kF))[xs];
      *reinterpret_cast<float4*>(vec + xrow * kK + xs * 20 + 16) = vx;
    }
    __syncthreads();  // x staged; also orders prev projection reads vs h-stage

    // x-part of gate GEMM -> partial (plain store; h-GEMM RMWs same slots)
#pragma unroll
    for (int bg = 0; bg < 4; ++bg) {
      unsigned long long acc[4][4];
#pragma unroll
      for (int bb = 0; bb < 4; ++bb)
#pragma unroll
        for (int cc = 0; cc < 4; ++cc) acc[bb][cc] = 0ull;
#pragma unroll
      for (int kp = 0; kp < kKPx; ++kp) {
#pragma unroll
        for (int bb = 0; bb < 4; ++bb) {
          const unsigned long long v =
              vec2[(bg * 4 + bb) * (kK / 2) + slice * 10 + 8 + kp];
#pragma unroll
          for (int cc = 0; cc < 4; ++cc) ffma2(acc[bb][cc], v, wx2[cc][kp]);
        }
      }
#pragma unroll
      for (int bb = 0; bb < 4; ++bb) {
        const float2 f0 = unpack2(acc[bb][0]);
        const float2 f1 = unpack2(acc[bb][1]);
        const float2 f2 = unpack2(acc[bb][2]);
        const float2 f3 = unpack2(acc[bb][3]);
        *reinterpret_cast<float4*>(
            partial + (slice * kBT + bg * 4 + bb) * 64 + cg * 4) =
            make_float4(f0.x + f0.y, f1.x + f1.y, f2.x + f2.y, f3.x + f3.y);
      }
    }

    // ============ wait for h(t), then h-dependent work ============
    spin();

    // stage h into interleaved h-slots: vec[row][s*20+0..15] = h[row][16s..]
    {
      const float4* src = reinterpret_cast<const float4*>(
          g_h[buf] + (bstripe * kBT + xrow) * kH + xs * 16);
      const float4 v0 = src[0], v1 = src[1], v2 = src[2], v3 = src[3];
      float4* dst = reinterpret_cast<float4*>(vec + xrow * kK + xs * 20);
      dst[0] = v0; dst[1] = v1; dst[2] = v2; dst[3] = v3;
    }
    __syncthreads();

    // h-part of gate GEMM, accumulate onto x partials (same-thread RMW)
#pragma unroll
    for (int bg = 0; bg < 4; ++bg) {
      unsigned long long acc[4][4];
#pragma unroll
      for (int bb = 0; bb < 4; ++bb)
#pragma unroll
        for (int cc = 0; cc < 4; ++cc) acc[bb][cc] = 0ull;
#pragma unroll
      for (int kp = 0; kp < kKPh; ++kp) {
#pragma unroll
        for (int bb = 0; bb < 4; ++bb) {
          const unsigned long long v =
              vec2[(bg * 4 + bb) * (kK / 2) + slice * 10 + kp];
#pragma unroll
          for (int cc = 0; cc < 4; ++cc) ffma2(acc[bb][cc], v, w2[cc][kp]);
        }
      }
#pragma unroll
      for (int bb = 0; bb < 4; ++bb) {
        float4* slot = reinterpret_cast<float4*>(
            partial + (slice * kBT + bg * 4 + bb) * 64 + cg * 4);
        const float4 xp = *slot;
        const float2 f0 = unpack2(acc[bb][0]);
        const float2 f1 = unpack2(acc[bb][1]);
        const float2 f2 = unpack2(acc[bb][2]);
        const float2 f3 = unpack2(acc[bb][3]);
        *slot = make_float4(xp.x + f0.x + f0.y, xp.y + f1.x + f1.y,
                            xp.z + f2.x + f2.y, xp.w + f3.x + f3.y);
      }
    }
    __syncthreads();

    // reduce 16 slices + LSTM cell update (c stays in register)
    {
      float gv[4];
#pragma unroll
      for (int g = 0; g < 4; ++g) {
        const float* pp = partial + bl * 64 + g * 16 + jj;
        float s = 0.0f;
#pragma unroll
        for (int sl = 0; sl < kNS; ++sl) s += pp[sl * kBT * 64];
        gv[g] = s + bias[g];
      }
      const float ig = sigmoidf_(gv[0]);
      const float fg = sigmoidf_(gv[1]);
      const float gg = tanhf_(gv[2]);
      const float og = sigmoidf_(gv[3]);
      cst = fg * cst + ig * gg;
      const float hv = og * tanhf_(cst);
      g_h[buf ^ 1][(bstripe * kBT + bl) * kH + jstripe * 16 + jj] = hv;
    }
    arrive();  // publish h(t+1); projection below is off the serial path

    if (dec) {
      // out_t = h_pre @ Wout^T + bout (4-way split-K + shuffle reduce)
      const int o = tid >> 2, p = tid & 3;
      const int ob = o >> 2, ofi = o & 3;
      float s = 0.0f;
#pragma unroll
      for (int si = 0; si < 4; ++si) {
        const int sl = p * 4 + si;
        const float4* v4 = reinterpret_cast<const float4*>(vec + ob * kK + sl * 20);
        const float4* w4 = reinterpret_cast<const float4*>(wout_s + ofi * kH + sl * 16);
#pragma unroll
        for (int i = 0; i < 4; ++i) {
          const float4 a = v4[i], b = w4[i];
          s += a.x * b.x + a.y * b.y + a.z * b.z + a.w * b.w;
        }
      }
      s += __shfl_xor_sync(0xffffffffu, s, 1);
      s += __shfl_xor_sync(0xffffffffu, s, 2);
      if (p == 0)
        out[((bstripe * kBT + ob) * kTlen + t) * kF + jstripe * 4 + ofi] =
            s + bout_s[ofi];
    }
  };

  load_w(Wih_e, Whh_e, b_e);
  arrive();  // publish h0

  for (int t = 0; t < kTlen; ++t) step(t, t & 1, false);

  load_w(Wih_d, Whh_d, b_d);
  for (int i = 0; i < kTlen; ++i) step(kTlen - 1 - i, i & 1, true);
}

extern "C" void kernel_launch(void* const* d_in, const int* in_sizes, int n_in,
                              void* d_out, int out_size) {
  cudaFuncSetAttribute(lstm_seq2seq_kernel,
                       cudaFuncAttributeMaxDynamicSharedMemorySize, kSmemBytes);
  init_barriers_kernel<<<1, 32>>>();
  lstm_seq2seq_kernel<<<kCtas, kThreads, kSmemBytes>>>(
      (const float*)d_in[0], (const float*)d_in[1], (const float*)d_in[2],
      (const float*)d_in[3], (const float*)d_in[4], (const float*)d_in[5],
      (const float*)d_in[6], (const float*)d_in[7], (const float*)d_in[8],
      (float*)d_out);
}

// round 7
// speedup vs baseline: 1.1202x; 1.1202x over previous
#include <cuda_runtime.h>
#include <cstdint>

#define DINLINE __device__ __forceinline__

namespace {
constexpr int kTlen = 1024;
constexpr int kF = 64;
constexpr int kH = 256;
constexpr int kK = 320;          // K = H + F (vec = [h | x])
constexpr int kNJ = 16;          // CTAs per barrier group (hidden stripes)
constexpr int kBT = 16;          // batch rows per CTA
constexpr int kNS = 16;          // k-slices (split-K)
constexpr int kKP = 10;          // f32x2 pairs per slice (20 k values)
constexpr int kThreads = 256;
constexpr int kCtas = 128;       // 8 batch stripes x 16 hidden stripes
constexpr int kSmemBytes = 120 * 1024;  // force 1 CTA/SM => all CTAs resident
}

__device__ float g_h[2][128 * 256];
__device__ unsigned g_cnt[8 * 64];  // one counter per group, 256B apart

__global__ void init_barriers_kernel() {
  if (threadIdx.x < 8) g_cnt[threadIdx.x * 64] = 0u;
}

DINLINE unsigned long long pack2(float lo, float hi) {
  unsigned long long r;
  asm("mov.b64 %0, {%1, %2};" : "=l"(r) : "f"(lo), "f"(hi));
  return r;
}
DINLINE void ffma2(unsigned long long& d, unsigned long long a, unsigned long long b) {
  asm("fma.rn.f32x2 %0, %1, %2, %0;" : "+l"(d) : "l"(a), "l"(b));
}
DINLINE float2 unpack2(unsigned long long v) {
  float lo, hi;
  asm("mov.b64 {%0, %1}, %2;" : "=f"(lo), "=f"(hi) : "l"(v));
  return make_float2(lo, hi);
}
DINLINE float sigmoidf_(float x) { return __fdividef(1.0f, 1.0f + __expf(-x)); }
DINLINE float tanhf_(float x) {
  const float e = __expf(2.0f * x);
  return 1.0f - __fdividef(2.0f, e + 1.0f);
}

__global__ void __launch_bounds__(kThreads, 1)
lstm_seq2seq_kernel(const float* __restrict__ ts,
                    const float* __restrict__ Wih_e, const float* __restrict__ Whh_e,
                    const float* __restrict__ b_e,
                    const float* __restrict__ Wih_d, const float* __restrict__ Whh_d,
                    const float* __restrict__ b_d,
                    const float* __restrict__ Wout, const float* __restrict__ bout,
                    float* __restrict__ out) {
  extern __shared__ float smem[];
  float* vec = smem;                         // [16][320]  vec = [h_t | x_t]
  float* partial = smem + kBT * kK;          // [16 slices][16 b][64]  col = j*4+gate
  float* wout_s = partial + kNS * kBT * 64;  // [4][256]
  float* bout_s = wout_s + 4 * kH;           // [4]

  const int tid = threadIdx.x;
  const int jstripe = blockIdx.x & (kNJ - 1);
  const int bstripe = blockIdx.x >> 4;

  const int slice = tid >> 4;   // 0..15  (GEMM k-slice)
  const int cg = tid & 15;      // 0..15  (local hidden col j in GEMM phase)
  const int bl = tid >> 4;      // update: local batch row
  const int jj = tid & 15;      // update: local hidden col

  unsigned* cnt = &g_cnt[bstripe * 64];
  unsigned barno = 0;

  // h0 = 0 for owned (b,j); stage W_out tile + b_out
  g_h[0][(bstripe * kBT + bl) * kH + jstripe * 16 + jj] = 0.0f;
  for (int idx = tid; idx < 4 * kH; idx += kThreads)
    wout_s[idx] = Wout[jstripe * 4 * kH + idx];
  if (tid < 4) bout_s[tid] = bout[jstripe * 4 + tid];

  unsigned long long w2[4][kKP];  // [gate][k-pair] weights, register-resident
  float bias[4];
  float cst = 0.0f;               // cell state, register-resident across ALL steps

  // cc = GATE index (0..3), local hidden col = cg  -> W row = cc*kH + j_global
  auto load_w = [&](const float* Wih, const float* Whh, const float* bv) {
#pragma unroll
    for (int cc = 0; cc < 4; ++cc) {
      const int row = cc * kH + jstripe * 16 + cg;
#pragma unroll
      for (int kp = 0; kp < kKP; ++kp) {
        const int k0 = slice * 20 + 2 * kp;
        float a, b;
        if (k0 < kH) { a = Whh[row * kH + k0];        b = Whh[row * kH + k0 + 1]; }
        else         { a = Wih[row * kF + (k0 - kH)]; b = Wih[row * kF + (k0 - kH) + 1]; }
        w2[cc][kp] = pack2(a, b);
      }
    }
    const int jg = jstripe * 16 + jj;
#pragma unroll
    for (int g = 0; g < 4; ++g) bias[g] = bv[g * kH + jg];
  };

  // monotonic single-atomic barrier (counter zeroed by init kernel per launch)
  auto arrive = [&]() {
    __syncthreads();           // all h stores of this CTA issued
    if (tid == 0) {
      ++barno;
      __threadfence();
      atomicAdd(cnt, 1u);
    }
  };
  auto wait = [&]() {
    if (tid == 0) {
      const unsigned target = (unsigned)kNJ * barno;
      unsigned v;
      do {
        asm volatile("ld.acquire.gpu.u32 %0, [%1];" : "=r"(v) : "l"(cnt));
      } while ((int)(v - target) < 0);
    }
    __syncthreads();
  };

  auto step = [&](int t, int buf, bool dec) {
    // prefetch x(t): LDG latency hides under the barrier spin
    const int xrow = tid >> 4, xcol = tid & 15;
    const float4 vx = reinterpret_cast<const float4*>(
        ts + (((bstripe * kBT + xrow) * kTlen + t) * kF))[xcol];

    wait();  // h(t) visible in g_h[buf]

    // stage vec = [h_t | x_t] into smem (coalesced)
    {
      const int r0 = tid >> 6, kc = tid & 63;
#pragma unroll
      for (int p = 0; p < 4; ++p) {
        const int row = p * 4 + r0;
        float4 v = reinterpret_cast<const float4*>(
            g_h[buf] + (bstripe * kBT + row) * kH)[kc];
        reinterpret_cast<float4*>(vec + row * kK)[kc] = v;
      }
      reinterpret_cast<float4*>(vec + xrow * kK + kH)[xcol] = vx;
    }
    __syncthreads();

    // gate GEMM partials: float4 operand loads, f32x2 FMAs, weights in regs
    const float4* vec4 = reinterpret_cast<const float4*>(vec);
#pragma unroll
    for (int bg = 0; bg < 4; ++bg) {
      unsigned long long acc[4][4];
#pragma unroll
      for (int bb = 0; bb < 4; ++bb)
#pragma unroll
        for (int cc = 0; cc < 4; ++cc) acc[bb][cc] = 0ull;
#pragma unroll
      for (int q = 0; q < 5; ++q) {   // 5 float4 = 20 k values per slice
#pragma unroll
        for (int bb = 0; bb < 4; ++bb) {
          const float4 vv = vec4[(bg * 4 + bb) * (kK / 4) + slice * 5 + q];
          const unsigned long long v0 = pack2(vv.x, vv.y);
          const unsigned long long v1 = pack2(vv.z, vv.w);
#pragma unroll
          for (int cc = 0; cc < 4; ++cc) {
            ffma2(acc[bb][cc], v0, w2[cc][2 * q]);
            ffma2(acc[bb][cc], v1, w2[cc][2 * q + 1]);
          }
        }
      }
#pragma unroll
      for (int bb = 0; bb < 4; ++bb) {
        // gate-interleaved: cols cg*4 .. cg*4+3 hold gates 0..3 of local j=cg
        const float2 f0 = unpack2(acc[bb][0]);
        const float2 f1 = unpack2(acc[bb][1]);
        const float2 f2 = unpack2(acc[bb][2]);
        const float2 f3 = unpack2(acc[bb][3]);
        *reinterpret_cast<float4*>(
            partial + (slice * kBT + bg * 4 + bb) * 64 + cg * 4) =
            make_float4(f0.x + f0.y, f1.x + f1.y, f2.x + f2.y, f3.x + f3.y);
      }
    }
    __syncthreads();

    // reduce 16 slices (one float4 per slice!) + LSTM cell update
    {
      const float4* p4 = reinterpret_cast<const float4*>(partial);
      float4 s = p4[bl * 16 + jj];
#pragma unroll
      for (int sl = 1; sl < kNS; ++sl) {
        const float4 v = p4[sl * 256 + bl * 16 + jj];
        s.x += v.x; s.y += v.y; s.z += v.z; s.w += v.w;
      }
      const float ig = sigmoidf_(s.x + bias[0]);
      const float fg = sigmoidf_(s.y + bias[1]);
      const float gg = tanhf_(s.z + bias[2]);
      const float og = sigmoidf_(s.w + bias[3]);
      cst = fg * cst + ig * gg;
      const float hv = og * tanhf_(cst);
      g_h[buf ^ 1][(bstripe * kBT + bl) * kH + jstripe * 16 + jj] = hv;
    }
    arrive();  // publish h(t+1); projection below is off the serial path

    if (dec) {
      // out_t = h_pre @ Wout^T + bout — vec still holds h_t
      const int o = tid >> 2, p = tid & 3;
      const int ob = o >> 2, ofi = o & 3;
      const float4* v4 = reinterpret_cast<const float4*>(vec + ob * kK + p * 64);
      const float4* w4 = reinterpret_cast<const float4*>(wout_s + ofi * kH + p * 64);
      float s = 0.0f;
#pragma unroll
      for (int i = 0; i < 16; ++i) {
        const float4 a = v4[i], b = w4[i];
        s += a.x * b.x + a.y * b.y + a.z * b.z + a.w * b.w;
      }
      s += __shfl_xor_sync(0xffffffffu, s, 1);
      s += __shfl_xor_sync(0xffffffffu, s, 2);
      if (p == 0)
        out[((bstripe * kBT + ob) * kTlen + t) * kF + jstripe * 4 + ofi] =
            s + bout_s[ofi];
    }
  };

  load_w(Wih_e, Whh_e, b_e);
  arrive();  // publish h0

  for (int t = 0; t < kTlen; ++t) step(t, t & 1, false);

  load_w(Wih_d, Whh_d, b_d);
  for (int i = 0; i < kTlen; ++i) step(kTlen - 1 - i, i & 1, true);
}

extern "C" void kernel_launch(void* const* d_in, const int* in_sizes, int n_in,
                              void* d_out, int out_size) {
  cudaFuncSetAttribute(lstm_seq2seq_kernel,
                       cudaFuncAttributeMaxDynamicSharedMemorySize, kSmemBytes);
  init_barriers_kernel<<<1, 32>>>();
  lstm_seq2seq_kernel<<<kCtas, kThreads, kSmemBytes>>>(
      (const float*)d_in[0], (const float*)d_in[1], (const float*)d_in[2],
      (const float*)d_in[3], (const float*)d_in[4], (const float*)d_in[5],
      (const float*)d_in[6], (const float*)d_in[7], (const float*)d_in[8],
      (float*)d_out);
}